// round 2
// baseline (speedup 1.0000x reference)
#include <cuda_runtime.h>

#define NSP 2048      // spatial points per row
#define BATCH 64      // batch rows
#define NSTEP 1000    // time steps
#define THREADS 512   // 4 elements per thread

__global__ __launch_bounds__(THREADS, 1)
void ks_step_kernel(const float* __restrict__ u0,
                    const float* __restrict__ cptr,
                    const float* __restrict__ aptr,
                    const float* __restrict__ bptr,
                    float* __restrict__ out) {
    __shared__ float sbuf[2][NSP];   // double-buffered row state (16 KB)

    const int b  = blockIdx.x;
    const int i0 = threadIdx.x * 4;

    const float dt = 0.01f;
    // u_new = u + dt*(-c*u*(up1-um1)*0.5 - alpha*uxx - beta*uxxxx)
    //       = u + A*(u*d1) + Bc*uxx + Cc*uxxxx
    const float A  = -0.5f * dt * (*cptr);
    const float Bc = -dt * (*aptr);
    const float Cc = -dt * (*bptr);

    // Load initial condition: this thread's 4 contiguous elements.
    float4 C = *reinterpret_cast<const float4*>(u0 + (size_t)b * NSP + i0);
    *reinterpret_cast<float4*>(&sbuf[0][i0]) = C;
    // Frame 0 of the trajectory is u0 itself (d_out is poisoned).
    *reinterpret_cast<float4*>(out + (size_t)b * NSP + i0) = C;
    __syncthreads();

    // Output pointer for frame 1, this row, this thread's slot.
    float* op = out + (size_t)BATCH * NSP + (size_t)b * NSP + i0;

    // Periodic halo indices (N is a power of two).
    const int il = (i0 - 4) & (NSP - 1);
    const int ir = (i0 + 4) & (NSP - 1);

    #pragma unroll 1
    for (int t = 0; t < NSTEP; t++) {
        const float* cur = sbuf[t & 1];
        float*       nxt = sbuf[(t & 1) ^ 1];

        // Halos from shared memory; center 4 values live in registers (C).
        float4 L = *reinterpret_cast<const float4*>(cur + il);
        float4 R = *reinterpret_cast<const float4*>(cur + ir);

        float x[8] = { L.z, L.w, C.x, C.y, C.z, C.w, R.x, R.y };
        float r[4];
        #pragma unroll
        for (int k = 0; k < 4; k++) {
            float um2 = x[k];
            float um1 = x[k + 1];
            float u   = x[k + 2];
            float up1 = x[k + 3];
            float up2 = x[k + 4];

            float d1 = up1 - um1;           // 2*dx * u_x
            float s1 = up1 + um1;
            float s2 = up2 + um2;
            float uxx   = fmaf(-2.0f, u, s1);                    // u_xx
            float uxxxx = fmaf(6.0f, u, fmaf(-4.0f, s1, s2));    // u_xxxx

            float rr = fmaf(A, u * d1, u);
            rr = fmaf(Bc, uxx, rr);
            rr = fmaf(Cc, uxxxx, rr);
            r[k] = rr;
        }

        float4 nv = make_float4(r[0], r[1], r[2], r[3]);
        *reinterpret_cast<float4*>(nxt + i0) = nv;   // next-step state
        *reinterpret_cast<float4*>(op)       = nv;   // trajectory frame t+1
        op += (size_t)BATCH * NSP;
        C = nv;                                      // keep center in regs
        __syncthreads();
    }
}

extern "C" void kernel_launch(void* const* d_in, const int* in_sizes, int n_in,
                              void* d_out, int out_size) {
    const float* u0    = (const float*)d_in[0];
    const float* c     = (const float*)d_in[1];
    const float* alpha = (const float*)d_in[2];
    const float* beta  = (const float*)d_in[3];
    float* out = (float*)d_out;

    ks_step_kernel<<<BATCH, THREADS>>>(u0, c, alpha, beta, out);
}

// round 3
// speedup vs baseline: 1.1067x; 1.1067x over previous
#include <cuda_runtime.h>
#include <cstdint>

#define NSP    2048
#define BATCH  64
#define NSTEP  1000
#define HALO   64                    // ghost width per side (= 2 * KEX)
#define KEX    32                    // steps between halo exchanges
#define OWN    1024                  // elements owned per CTA (NSP / 2)
#define LBUF   (OWN + 2 * HALO)      // 1152 buffered elements
#define THREADS (LBUF / 4)           // 288 threads, 4 elements each

__global__ void __cluster_dims__(2, 1, 1) __launch_bounds__(THREADS, 1)
ks_kernel(const float* __restrict__ u0,
          const float* __restrict__ cptr,
          const float* __restrict__ aptr,
          const float* __restrict__ bptr,
          float* __restrict__ out) {
    __shared__ float sbuf[2][LBUF];      // double-buffered state (9.2 KB)

    const int row  = blockIdx.x >> 1;    // batch row
    const int half = blockIdx.x & 1;     // which half of the row
    const int base = half * OWN;         // global offset of owned region
    const int j0   = threadIdx.x * 4;    // this thread's buffer slot

    uint32_t rank;
    asm("mov.u32 %0, %%cluster_ctarank;" : "=r"(rank));
    const uint32_t peer = rank ^ 1u;

    const float dt = 0.01f;
    const float A  = -0.5f * dt * (*cptr);   // advection coeff on u*(up1-um1)
    const float Bc = -dt * (*aptr);          // diffusion
    const float Cc = -dt * (*bptr);          // hyperdiffusion

    // ---- initial load: buffer j <-> global (base + j - HALO) mod NSP ----
    const int g0 = (base + j0 - HALO) & (NSP - 1);        // multiple of 4
    float4 C = *reinterpret_cast<const float4*>(u0 + (size_t)row * NSP + g0);
    *reinterpret_cast<float4*>(&sbuf[0][j0]) = C;

    const bool owned = (j0 >= HALO) && (j0 < HALO + OWN);
    // frame 0 = u0 (owned region only; each global idx owned by exactly one CTA)
    if (owned)
        *reinterpret_cast<float4*>(out + (size_t)row * NSP + g0) = C;
    __syncthreads();

    // output pointer for frame 1, this thread's owned slot (no wrap for owned)
    float* op = out + (size_t)BATCH * NSP + (size_t)row * NSP + (base + j0 - HALO);

    // neighbor float4 slots, clamped at buffer ends (edge cells are ghost garbage)
    const int il = (threadIdx.x == 0)           ? 0        : j0 - 4;
    const int ir = (threadIdx.x == THREADS - 1) ? j0       : j0 + 4;

    #pragma unroll 1
    for (int t = 0; t < NSTEP; t++) {
        const int par = t & 1;

        if (t > 0 && (t & (KEX - 1)) == 0) {
            // ---- halo exchange on cur = sbuf[par] (par==0 since KEX even) ----
            // sync #1: peer's owned region in cur is complete & visible
            asm volatile("barrier.cluster.arrive.aligned;" ::: "memory");
            asm volatile("barrier.cluster.wait.aligned;"   ::: "memory");

            if (threadIdx.x < 32) {
                int i = threadIdx.x;
                int dst4, src4;
                if (i < 16) {   // my left ghost [0,64) <- peer owned rightmost
                    dst4 = i;
                    src4 = (LBUF - 2 * HALO) / 4 + i;          // 256 + i
                } else {        // my right ghost [1088,1152) <- peer owned leftmost
                    dst4 = (LBUF - HALO) / 4 + (i - 16);       // 272 + ...
                    src4 = HALO / 4 + (i - 16);                // 16 + ...
                }
                uint32_t sb = (uint32_t)__cvta_generic_to_shared(&sbuf[par][0]);
                uint32_t paddr;
                asm("mapa.shared::cluster.u32 %0, %1, %2;"
                    : "=r"(paddr) : "r"(sb + src4 * 16), "r"(peer));
                float x, y, z, w;
                asm volatile("ld.shared::cluster.v4.f32 {%0,%1,%2,%3}, [%4];"
                             : "=f"(x), "=f"(y), "=f"(z), "=f"(w) : "r"(paddr));
                float4 v = make_float4(x, y, z, w);
                reinterpret_cast<float4*>(&sbuf[par][0])[dst4] = v;
            }
            __syncthreads();   // ghost refills visible CTA-wide

            // sync #2: both CTAs done reading before anyone overwrites cur
            asm volatile("barrier.cluster.arrive.aligned;" ::: "memory");
            asm volatile("barrier.cluster.wait.aligned;"   ::: "memory");

            // ghost-region threads had garbage C; refresh everyone from cur
            C = *reinterpret_cast<float4*>(&sbuf[par][j0]);
        }

        const float* cur = sbuf[par];
        float*       nxt = sbuf[par ^ 1];

        float4 L = *reinterpret_cast<const float4*>(cur + il);
        float4 R = *reinterpret_cast<const float4*>(cur + ir);

        float x[8] = { L.z, L.w, C.x, C.y, C.z, C.w, R.x, R.y };
        float r[4];
        #pragma unroll
        for (int k = 0; k < 4; k++) {
            float um2 = x[k];
            float um1 = x[k + 1];
            float u   = x[k + 2];
            float up1 = x[k + 3];
            float up2 = x[k + 4];

            float d1 = up1 - um1;
            float s1 = up1 + um1;
            float s2 = up2 + um2;
            float uxx   = fmaf(-2.0f, u, s1);
            float uxxxx = fmaf(6.0f, u, fmaf(-4.0f, s1, s2));

            float rr = fmaf(A, u * d1, u);
            rr = fmaf(Bc, uxx, rr);
            rr = fmaf(Cc, uxxxx, rr);
            r[k] = rr;
        }

        float4 nv = make_float4(r[0], r[1], r[2], r[3]);
        *reinterpret_cast<float4*>(nxt + j0) = nv;
        if (owned)
            *reinterpret_cast<float4*>(op) = nv;
        op += (size_t)BATCH * NSP;
        C = nv;
        __syncthreads();
    }
}

extern "C" void kernel_launch(void* const* d_in, const int* in_sizes, int n_in,
                              void* d_out, int out_size) {
    const float* u0    = (const float*)d_in[0];
    const float* c     = (const float*)d_in[1];
    const float* alpha = (const float*)d_in[2];
    const float* beta  = (const float*)d_in[3];
    float* out = (float*)d_out;

    ks_kernel<<<BATCH * 2, THREADS>>>(u0, c, alpha, beta, out);
}

// round 4
// speedup vs baseline: 1.3742x; 1.2417x over previous
#include <cuda_runtime.h>
#include <cstdint>

#define NSP     2048
#define BATCH   64
#define NSTEP   1000
#define KEX     32            // steps between ghost exchanges
#define GW      64            // ghost width per side (= 2*KEX)
#define OWNW    256           // owned elems per warp
#define COVER   384           // OWNW + 2*GW
#define EPT     12            // elems per thread (COVER/32)
#define THREADS 128           // 4 warps per CTA
#define OWN_CTA 1024          // owned per CTA (half row)

typedef unsigned long long u64;

__device__ __forceinline__ u64 pk(float lo, float hi) {
    u64 r; asm("mov.b64 %0,{%1,%2};" : "=l"(r) : "f"(lo), "f"(hi)); return r;
}
__device__ __forceinline__ void upk(u64 v, float& lo, float& hi) {
    asm("mov.b64 {%0,%1},%2;" : "=f"(lo), "=f"(hi) : "l"(v));
}
__device__ __forceinline__ u64 fma2(u64 a, u64 b, u64 c) {
    u64 d; asm("fma.rn.f32x2 %0,%1,%2,%3;" : "=l"(d) : "l"(a), "l"(b), "l"(c)); return d;
}
__device__ __forceinline__ u64 add2(u64 a, u64 b) {
    u64 d; asm("add.rn.f32x2 %0,%1,%2;" : "=l"(d) : "l"(a), "l"(b)); return d;
}
__device__ __forceinline__ u64 mul2(u64 a, u64 b) {
    u64 d; asm("mul.rn.f32x2 %0,%1,%2;" : "=l"(d) : "l"(a), "l"(b)); return d;
}

__global__ void __cluster_dims__(2, 1, 1) __launch_bounds__(THREADS, 1)
ks_kernel(const float* __restrict__ u0,
          const float* __restrict__ cp,
          const float* __restrict__ ap,
          const float* __restrict__ bp,
          float* __restrict__ out) {
    __shared__ alignas(16) float sh[OWN_CTA];   // exchange staging (4 KB)

    const int row  = blockIdx.x >> 1;
    const int half = blockIdx.x & 1;
    const int w    = threadIdx.x >> 5;
    const int lane = threadIdx.x & 31;

    const float dt = 0.01f;
    const float Af = -0.5f * dt * (*cp);
    const float Bc = -dt * (*ap);
    const float Cc = -dt * (*bp);
    // u_new = c0*u + c1*(up1+um1) + c2*(up2+um2) + Af*u*(up1-um1)
    const float c0f = 1.0f - 2.0f * Bc + 6.0f * Cc;
    const float c1f = Bc - 4.0f * Cc;
    const float c2f = Cc;
    const u64 C0 = pk(c0f, c0f), C1 = pk(c1f, c1f), C2 = pk(c2f, c2f);
    const u64 AV = pk(Af, Af), M1 = pk(-1.0f, -1.0f);

    // warp cover: local coord j in [0, COVER); global row pos = base + j (mod NSP)
    const int base = half * OWN_CTA + w * OWNW - GW;    // may be negative
    const int j0   = lane * EPT;

    // ---- initial load: 3 float4 groups per thread, periodic wrap ----
    u64 P[6];
    const float* urow = u0 + (size_t)row * NSP;
    #pragma unroll
    for (int g = 0; g < 3; g++) {
        int pos = (base + j0 + 4 * g) & (NSP - 1);
        float4 v = *reinterpret_cast<const float4*>(urow + pos);
        P[2 * g]     = pk(v.x, v.y);
        P[2 * g + 1] = pk(v.z, v.w);
    }

    // ---- frame 0 = u0 (owned groups only; d_out is poisoned) ----
    {
        float* o0 = out + (size_t)row * NSP;
        #pragma unroll
        for (int g = 0; g < 3; g++) {
            int j = j0 + 4 * g;
            if (j >= GW && j < GW + OWNW) {
                ulonglong2 v; v.x = P[2 * g]; v.y = P[2 * g + 1];
                *reinterpret_cast<ulonglong2*>(o0 + base + j) = v;
            }
        }
    }

    const uint32_t shbase = (uint32_t)__cvta_generic_to_shared(sh);
    const uint32_t peer   = (uint32_t)(half ^ 1);

    // initial cluster arrive — pairs with the first exchange's wait
    asm volatile("barrier.cluster.arrive.aligned;" ::: "memory");

    float* ofr = out + (size_t)BATCH * NSP + (size_t)row * NSP;   // frame 1

    #pragma unroll 1
    for (int t = 0; t < NSTEP; t++) {
        if (t > 0 && (t & (KEX - 1)) == 0) {
            // ===== ghost exchange (every KEX steps) =====
            // wait: peer finished reading my sh from the previous exchange
            asm volatile("barrier.cluster.wait.aligned;" ::: "memory");

            // publish my owned 256 elems to sh
            #pragma unroll
            for (int g = 0; g < 3; g++) {
                int j = j0 + 4 * g;
                if (j >= GW && j < GW + OWNW) {
                    float a, b, c, d;
                    upk(P[2 * g], a, b); upk(P[2 * g + 1], c, d);
                    *reinterpret_cast<float4*>(&sh[w * OWNW + (j - GW)]) =
                        make_float4(a, b, c, d);
                }
            }
            __syncthreads();
            asm volatile("barrier.cluster.arrive.aligned;" ::: "memory");
            asm volatile("barrier.cluster.wait.aligned;"   ::: "memory"); // both sh ready

            // refill ghost groups from own sh or peer sh (DSMEM)
            #pragma unroll
            for (int g = 0; g < 3; g++) {
                int j = j0 + 4 * g;
                if (j < GW || j >= GW + OWNW) {
                    int pos = (base + j) & (NSP - 1);
                    int h2  = pos >> 10;            // owning half
                    int idx = pos & (OWN_CTA - 1);
                    float4 v;
                    if (h2 == half) {
                        v = *reinterpret_cast<const float4*>(&sh[idx]);
                    } else {
                        uint32_t pa;
                        asm("mapa.shared::cluster.u32 %0, %1, %2;"
                            : "=r"(pa) : "r"(shbase + (uint32_t)idx * 4u), "r"(peer));
                        asm volatile("ld.shared::cluster.v4.f32 {%0,%1,%2,%3}, [%4];"
                                     : "=f"(v.x), "=f"(v.y), "=f"(v.z), "=f"(v.w)
                                     : "r"(pa));
                    }
                    P[2 * g]     = pk(v.x, v.y);
                    P[2 * g + 1] = pk(v.z, v.w);
                }
            }
            __syncthreads();
            // arrive: my CTA is done reading peer sh
            asm volatile("barrier.cluster.arrive.aligned;" ::: "memory");
        }

        // ===== one explicit-Euler step, fully in registers =====
        // extended element array e[0..15]: e[2..13] = my 12 elems
        float e[16];
        #pragma unroll
        for (int p = 0; p < 6; p++) upk(P[p], e[2 + 2 * p], e[3 + 2 * p]);
        e[0]  = __shfl_up_sync(0xffffffffu, e[12], 1);
        e[1]  = __shfl_up_sync(0xffffffffu, e[13], 1);
        e[14] = __shfl_down_sync(0xffffffffu, e[2], 1);
        e[15] = __shfl_down_sync(0xffffffffu, e[3], 1);

        // aligned ext pairs A[i] = (e[2i], e[2i+1]), i=0..7
        u64 A[8];
        A[0] = pk(e[0], e[1]);
        #pragma unroll
        for (int p = 0; p < 6; p++) A[p + 1] = P[p];
        A[7] = pk(e[14], e[15]);
        // odd ext pairs O[i] = (e[2i+1], e[2i+2]), i=0..6
        u64 O[7];
        #pragma unroll
        for (int i = 0; i < 7; i++) O[i] = pk(e[2 * i + 1], e[2 * i + 2]);

        u64 r[6];
        #pragma unroll
        for (int p = 0; p < 6; p++) {
            u64 u   = A[p + 1];
            u64 um2 = A[p];
            u64 up2 = A[p + 2];
            u64 um1 = O[p];
            u64 up1 = O[p + 1];

            u64 s1  = add2(up1, um1);
            u64 s2  = add2(up2, um2);
            u64 d1  = fma2(M1, um1, up1);        // up1 - um1
            u64 lin = mul2(C0, u);
            lin = fma2(C1, s1, lin);
            lin = fma2(C2, s2, lin);
            u64 tn  = mul2(AV, u);
            r[p] = fma2(tn, d1, lin);
        }

        // stream trajectory frame (owned groups), update state
        #pragma unroll
        for (int g = 0; g < 3; g++) {
            int j = j0 + 4 * g;
            if (j >= GW && j < GW + OWNW) {
                ulonglong2 v; v.x = r[2 * g]; v.y = r[2 * g + 1];
                *reinterpret_cast<ulonglong2*>(ofr + base + j) = v;
            }
        }
        #pragma unroll
        for (int p = 0; p < 6; p++) P[p] = r[p];
        ofr += (size_t)BATCH * NSP;
    }

    // pair the final outstanding arrive
    asm volatile("barrier.cluster.wait.aligned;" ::: "memory");
}

extern "C" void kernel_launch(void* const* d_in, const int* in_sizes, int n_in,
                              void* d_out, int out_size) {
    const float* u0    = (const float*)d_in[0];
    const float* c     = (const float*)d_in[1];
    const float* alpha = (const float*)d_in[2];
    const float* beta  = (const float*)d_in[3];
    float* out = (float*)d_out;

    ks_kernel<<<BATCH * 2, THREADS>>>(u0, c, alpha, beta, out);
}